// round 13
// baseline (speedup 1.0000x reference)
#include <cuda_runtime.h>
#include <cuda_fp16.h>

// AntiAliasInterpolation2d: depthwise 13x13 Gaussian, stride 4, zero pad 6.
// Input [32,3,512,512] f32, weight [3,1,13,13] f32, output [32,3,128,128] f32.
//
// Separable (exact): 2D kernel = outer(g,g), g[j] = k2[6][j]/sqrt(k2[6][6]).
// R13: vpass widened: thread = 8 columns (one uint4 of halves) x one oy-pair
// (2 rows sharing 9 of 17 window rows) = 16 outputs from 17 independent 16B
// loads. hpass unchanged from R12 (2 rows/warp, 8 loads in flight, ldcs).

#define IW   512
#define IW4  128                 // input row in float4
#define OW   128

__device__ __half g_tmp[96 * 512 * 128];   // 12.6 MB scratch

__device__ __forceinline__ float4 ldcs4(const float4* p) { return __ldcs(p); }

// K1: warp = TWO adjacent input rows; CTA = 16 rows; 3072 CTAs.
__global__ __launch_bounds__(256, 6)
void hpass_kernel(const float* __restrict__ inp, const float* __restrict__ w)
{
    const int tid  = threadIdx.x;
    const int lane = tid & 31;
    const int wid  = tid >> 5;

    const int wg = blockIdx.x * 8 + wid;      // global warp id
    const int r0 = 2 * wg;                    // rows r0, r0+1 (same image: 2|512)
    const int c  = (r0 >> 9) % 3;

    float g[7];
    {
        const float inv = 1.0f / sqrtf(w[c * 169 + 84]);
#pragma unroll
        for (int k = 0; k < 7; k++) g[k] = w[c * 169 + 78 + k] * inv;
    }

    const float4* ra = reinterpret_cast<const float4*>(inp) + (size_t)r0 * IW4;
    const float4* rb = ra + IW4;
    __half* da = g_tmp + (size_t)r0 * OW;

    const float4 z4 = make_float4(0.f, 0.f, 0.f, 0.f);

#pragma unroll
    for (int j = 0; j < 4; j++) {
        const int ox = lane + 32 * j;
        float4 a0 = (ox >= 2)       ? ldcs4(ra + ox - 2) : z4;
        float4 a1 = (ox >= 1)       ? ldcs4(ra + ox - 1) : z4;
        float4 a2 =                   ldcs4(ra + ox);
        float4 a3 = (ox <= IW4 - 2) ? ldcs4(ra + ox + 1) : z4;
        float4 b0 = (ox >= 2)       ? ldcs4(rb + ox - 2) : z4;
        float4 b1 = (ox >= 1)       ? ldcs4(rb + ox - 1) : z4;
        float4 b2 =                   ldcs4(rb + ox);
        float4 b3 = (ox <= IW4 - 2) ? ldcs4(rb + ox + 1) : z4;

        float e0 =       g[0] * a0.z;
        float e1 =       g[1] * a0.w;
        e0 = fmaf(g[2], a1.x, e0);
        e1 = fmaf(g[3], a1.y, e1);
        e0 = fmaf(g[4], a1.z, e0);
        e1 = fmaf(g[5], a1.w, e1);
        e0 = fmaf(g[6], a2.x, e0);
        e1 = fmaf(g[5], a2.y, e1);
        e0 = fmaf(g[4], a2.z, e0);
        e1 = fmaf(g[3], a2.w, e1);
        e0 = fmaf(g[2], a3.x, e0);
        e1 = fmaf(g[1], a3.y, e1);
        e0 = fmaf(g[0], a3.z, e0);

        float f0 =       g[0] * b0.z;
        float f1 =       g[1] * b0.w;
        f0 = fmaf(g[2], b1.x, f0);
        f1 = fmaf(g[3], b1.y, f1);
        f0 = fmaf(g[4], b1.z, f0);
        f1 = fmaf(g[5], b1.w, f1);
        f0 = fmaf(g[6], b2.x, f0);
        f1 = fmaf(g[5], b2.y, f1);
        f0 = fmaf(g[4], b2.z, f0);
        f1 = fmaf(g[3], b2.w, f1);
        f0 = fmaf(g[2], b3.x, f0);
        f1 = fmaf(g[1], b3.y, f1);
        f0 = fmaf(g[0], b3.z, f0);

        da[ox]      = __float2half_rn(e0 + e1);
        da[OW + ox] = __float2half_rn(f0 + f1);
    }
}

// K2: thread = 8 columns x oy-pair = 16 outputs from 17 uint4 loads.
// 96 images * 64 pairs * 16 col-groups = 98304 threads -> 384 CTAs.
__global__ __launch_bounds__(256, 5)
void vpass_kernel(const float* __restrict__ w, float* __restrict__ out)
{
    __shared__ float sw[8];
    const int tid = threadIdx.x;
    const int idx = blockIdx.x * 256 + tid;
    const int ox8 = idx & 15;                 // group of 8 columns (one uint4)
    const int t   = idx >> 4;                 // nc*64 + oyp
    const int oyp = t & 63;
    const int nc  = t >> 6;
    const int oy0 = 2 * oyp;

    const int c = (blockIdx.x / 4) % 3;       // 16 pairs/CTA, 64 pairs/image
    if (tid < 7)
        sw[tid] = w[c * 169 + 78 + tid] / sqrtf(w[c * 169 + 84]);
    __syncthreads();

    float g[7];
#pragma unroll
    for (int k = 0; k < 7; k++) g[k] = sw[k];

    // tmp rows: 128 halves = 16 uint4 per row
    const uint4* base = reinterpret_cast<const uint4*>(g_tmp + (size_t)nc * (IW * OW)) + ox8;
    const int ib = 4 * oy0 - 6;               // first window row of out0

    float p0[8], p1[8];
#pragma unroll
    for (int i = 0; i < 8; i++) { p0[i] = 0.f; p1[i] = 0.f; }

#pragma unroll
    for (int k = 0; k < 17; k++) {
        const int iy = ib + k;
        if (iy >= 0 && iy < IW) {
            uint4 raw = base[(size_t)iy * 16];
            float2 fA = __half22float2(*reinterpret_cast<__half2*>(&raw.x));
            float2 fB = __half22float2(*reinterpret_cast<__half2*>(&raw.y));
            float2 fC = __half22float2(*reinterpret_cast<__half2*>(&raw.z));
            float2 fD = __half22float2(*reinterpret_cast<__half2*>(&raw.w));
            float f[8] = {fA.x, fA.y, fB.x, fB.y, fC.x, fC.y, fD.x, fD.y};
            if (k <= 12) {
                const float gk = g[k < 7 ? k : 12 - k];
#pragma unroll
                for (int i = 0; i < 8; i++) p0[i] = fmaf(gk, f[i], p0[i]);
            }
            if (k >= 4) {
                const int m = k - 4;
                const float gm = g[m < 7 ? m : 12 - m];
#pragma unroll
                for (int i = 0; i < 8; i++) p1[i] = fmaf(gm, f[i], p1[i]);
            }
        }
    }

    float4* ob = reinterpret_cast<float4*>(out) + ((size_t)nc * 128 + oy0) * 32 + 2 * ox8;
    ob[0]  = make_float4(p0[0], p0[1], p0[2], p0[3]);
    ob[1]  = make_float4(p0[4], p0[5], p0[6], p0[7]);
    ob[32] = make_float4(p1[0], p1[1], p1[2], p1[3]);
    ob[33] = make_float4(p1[4], p1[5], p1[6], p1[7]);
}

extern "C" void kernel_launch(void* const* d_in, const int* in_sizes, int n_in,
                              void* d_out, int out_size)
{
    const float* inp = (const float*)d_in[0];   // [32,3,512,512]
    const float* wgt = (const float*)d_in[1];   // [3,1,13,13]
    float* out = (float*)d_out;                 // [32,3,128,128]

    hpass_kernel<<<96 * 512 / 16, 256>>>(inp, wgt);       // 3072 CTAs
    vpass_kernel<<<96 * 64 * 16 / 256, 256>>>(wgt, out);  // 384 CTAs
}